// round 16
// baseline (speedup 1.0000x reference)
#include <cuda_runtime.h>
#include <cuda_fp16.h>
#include <cstdint>
#include <string.h>
#include <math.h>

#define N_EMBD 1024
#define N_HEAD 16
#define HEADD  64
#define BATCH  4
#define SEQ    2048
#define ROWS   (BATCH * SEQ)          // 8192
#define C3     (3 * N_EMBD)           // 3072

// scratch (allocation-free rule: device globals) — fp16 operand copies
__device__ __half g_qkvh[(size_t)ROWS * C3];        // qkv, half
__device__ __half g_atth[(size_t)ROWS * N_EMBD];    // attention out, half
__device__ __half g_xh  [(size_t)ROWS * N_EMBD];    // x, half
__device__ __half g_wqth[(size_t)C3 * N_EMBD];      // W_qkv^T [3072,1024], half
__device__ __half g_woth[(size_t)N_EMBD * N_EMBD];  // W_out^T [1024,1024], half
__device__ __half g_vth [(size_t)BATCH * N_HEAD * HEADD * SEQ];  // V^T per head

// ---------------------------------------------------------------------------
__device__ __forceinline__ uint32_t h2_bits(__half2 v) {
    uint32_t u;
    memcpy(&u, &v, 4);
    return u;
}
__device__ __forceinline__ uint32_t smem_u32(const void* p) {
    uint32_t a;
    asm("{ .reg .u64 t; cvta.to.shared.u64 t, %1; cvt.u32.u64 %0, t; }" : "=r"(a) : "l"(p));
    return a;
}
__device__ __forceinline__ void cp_async16(uint32_t dst, const void* src) {
    asm volatile("cp.async.cg.shared.global [%0], [%1], 16;" :: "r"(dst), "l"(src));
}
#define CP_COMMIT() asm volatile("cp.async.commit_group;" ::: "memory")
#define CP_WAIT(n)  asm volatile("cp.async.wait_group %0;" :: "n"(n) : "memory")

__device__ __forceinline__ void mma_f16(float* d, const uint32_t* a, const uint32_t* b) {
    asm volatile(
        "mma.sync.aligned.m16n8k16.row.col.f32.f16.f16.f32 "
        "{%0,%1,%2,%3}, {%4,%5,%6,%7}, {%8,%9}, {%0,%1,%2,%3};"
        : "+f"(d[0]), "+f"(d[1]), "+f"(d[2]), "+f"(d[3])
        : "r"(a[0]), "r"(a[1]), "r"(a[2]), "r"(a[3]), "r"(b[0]), "r"(b[1]));
}
__device__ __forceinline__ void ldsm_x4(uint32_t* r, uint32_t addr) {
    asm volatile("ldmatrix.sync.aligned.m8n8.x4.shared.b16 {%0,%1,%2,%3}, [%4];"
                 : "=r"(r[0]), "=r"(r[1]), "=r"(r[2]), "=r"(r[3]) : "r"(addr));
}

// ---------------------------------------------------------------------------
// fused pre-pass: one launch does x->half convert + both weight transposes.
// ---------------------------------------------------------------------------
__device__ __forceinline__ void transpose_tile(const float* __restrict__ W,
                                               __half* __restrict__ Wt,
                                               int N, int nx, int ky,
                                               float (*t)[33]) {
    const int tx = threadIdx.x & 31, ty = threadIdx.x >> 5;
#pragma unroll
    for (int i = 0; i < 32; i += 8)
        t[ty + i][tx] = W[(size_t)(ky + ty + i) * N + nx + tx];
    __syncthreads();
#pragma unroll
    for (int i = 0; i < 32; i += 8)
        Wt[(size_t)(nx + ty + i) * 1024 + ky + tx] = __float2half_rn(t[tx][ty + i]);
}

__global__ __launch_bounds__(256) void prepass(
    const float* __restrict__ x, __half2* __restrict__ xh,
    const float* __restrict__ Wq, __half* __restrict__ wqt,
    const float* __restrict__ Wo, __half* __restrict__ wot)
{
    __shared__ float t[32][33];
    int bid = blockIdx.x;
    if (bid < 8192) {
        int i = bid * 256 + threadIdx.x;
        float4 v = ((const float4*)x)[i];
        xh[2 * i]     = __floats2half2_rn(v.x, v.y);
        xh[2 * i + 1] = __floats2half2_rn(v.z, v.w);
    } else if (bid < 8192 + 3072) {
        bid -= 8192;
        transpose_tile(Wq, wqt, C3, (bid % 96) * 32, (bid / 96) * 32, t);
    } else {
        bid -= 8192 + 3072;
        transpose_tile(Wo, wot, N_EMBD, (bid & 31) * 32, (bid >> 5) * 32, t);
    }
}

// ---------------------------------------------------------------------------
// FP16 mma.sync GEMM + bias: C[M,N] = A[M,K] @ Bt[N,K]^T + bias[N]
// 128x64 CTA tile, 4 warps (2x2 of 64x32 warp tiles), BK=32 halves,
// 3-stage cp.async pipeline, 4 CTAs/SM (cross-CTA latency hiding).
// FUSE_VT: for cols >= 2048 (V slice of qkv) also scatter transposed halves
// into vt[bh][d][t].
// ---------------------------------------------------------------------------
#define TSH      40                              // halves per row (80 B)
#define A_BYTES  (128 * TSH * 2)                 // 10240 B
#define B_BYTES  (64 * TSH * 2)                  // 5120 B
#define STAGE_SZ (A_BYTES + B_BYTES)             // 15360 B
#define GEMM_SMEM (3 * STAGE_SZ)                 // 46080 B

template <bool HALF_OUT, bool FUSE_VT>
__global__ __launch_bounds__(128, 4) void gemm_f16(
    const __half* __restrict__ A, const __half* __restrict__ Bt,
    const float* __restrict__ bias, void* __restrict__ Cv,
    __half* __restrict__ vt,
    int M, int N, int K)
{
    extern __shared__ char smem[];
    const uint32_t sb = smem_u32(smem);

    const int tid  = threadIdx.x;
    const int lane = tid & 31;
    const int warp = tid >> 5;
    const int wm   = (warp >> 1) * 64;   // 2 m-warps
    const int wn   = (warp & 1) * 32;    // 2 n-warps

    const int m0 = blockIdx.y * 128;
    const int n0 = blockIdx.x * 64;

    const int gid = lane >> 2;
    const int gtd = lane & 3;

    float acc[4][4][4];
#pragma unroll
    for (int mi = 0; mi < 4; mi++)
#pragma unroll
        for (int ni = 0; ni < 4; ni++)
#pragma unroll
            for (int r = 0; r < 4; r++) acc[mi][ni][r] = 0.f;

    // fp16 ldmatrix lane offsets (bytes), row stride 80 B (conflict-free)
    const uint32_t a_off = (uint32_t)(lane & 15) * (TSH * 2) +
                           ((uint32_t)(lane >> 4) << 4);
    const uint32_t b4_off = (uint32_t)((lane & 7) + ((lane >> 4) << 3)) * (TSH * 2) +
                            (((uint32_t)(lane >> 3) & 1) << 4);

#define PREFETCH(c, buf)                                                       \
    {                                                                          \
        const __half* Ag = A + (size_t)m0 * K + (c) * 32;                      \
        const __half* Bg = Bt + (size_t)n0 * K + (c) * 32;                     \
        const uint32_t pA = sb + (buf) * STAGE_SZ;                             \
        const uint32_t pB = pA + A_BYTES;                                      \
        _Pragma("unroll")                                                      \
        for (int i = 0; i < 4; i++) {                                          \
            int s  = tid + i * 128;                                            \
            int r  = s >> 2, p = s & 3;                                        \
            cp_async16(pA + r * (TSH * 2) + p * 16,                            \
                       Ag + (size_t)r * K + p * 8);                            \
        }                                                                      \
        _Pragma("unroll")                                                      \
        for (int i = 0; i < 2; i++) {                                          \
            int s  = tid + i * 128;                                            \
            int r  = s >> 2, p = s & 3;                                        \
            cp_async16(pB + r * (TSH * 2) + p * 16,                            \
                       Bg + (size_t)r * K + p * 8);                            \
        }                                                                      \
        CP_COMMIT();                                                           \
    }

#define LOAD_FRAGS(kk, bufi)                                                   \
    {                                                                          \
        const uint32_t kb = (uint32_t)(kk) * 32;                               \
        _Pragma("unroll")                                                      \
        for (int mi = 0; mi < 4; mi++)                                         \
            ldsm_x4(af[bufi][mi],                                              \
                    sA + (uint32_t)(wm + mi * 16) * (TSH * 2) + a_off + kb);   \
        _Pragma("unroll")                                                      \
        for (int p = 0; p < 2; p++)                                            \
            ldsm_x4(bf[bufi][p],                                               \
                    sB + (uint32_t)(wn + p * 16) * (TSH * 2) + b4_off + kb);   \
    }

    uint32_t af[2][4][4];
    uint32_t bf[2][2][4];

    const int NK = K >> 5;   // BK = 32 halves
    PREFETCH(0, 0);
    PREFETCH(1, 1);

    for (int c = 0; c < NK; c++) {
        if (c + 1 < NK) CP_WAIT(1); else CP_WAIT(0);
        __syncthreads();
        if (c + 2 < NK) PREFETCH(c + 2, (c + 2) % 3);

        const int buf = c % 3;
        const uint32_t sA = sb + buf * STAGE_SZ;
        const uint32_t sB = sA + A_BYTES;

        LOAD_FRAGS(0, 0);
#pragma unroll
        for (int kk = 0; kk < 2; kk++) {        // 2 x k16
            if (kk < 1) LOAD_FRAGS(kk + 1, 1);
            const int cur = kk & 1;
#pragma unroll
            for (int mi = 0; mi < 4; mi++)
#pragma unroll
                for (int ni = 0; ni < 4; ni++)
                    mma_f16(acc[mi][ni], af[cur][mi],
                            &bf[cur][ni >> 1][(ni & 1) << 1]);
        }
    }

    // epilogue: fp32 bias add; store half or float; optional fused V-transpose
#pragma unroll
    for (int mi = 0; mi < 4; mi++) {
#pragma unroll
        for (int ni = 0; ni < 4; ni++) {
            const int row = m0 + wm + mi * 16 + gid;
            const int col = n0 + wn + ni * 8 + (gtd << 1);
            const float b0 = bias[col];
            const float b1 = bias[col + 1];
            float v00 = acc[mi][ni][0] + b0, v01 = acc[mi][ni][1] + b1;
            float v10 = acc[mi][ni][2] + b0, v11 = acc[mi][ni][3] + b1;
            if (HALF_OUT) {
                __half* C = (__half*)Cv;
                __half2 h0 = __floats2half2_rn(v00, v01);
                __half2 h1 = __floats2half2_rn(v10, v11);
                *(__half2*)(C + (size_t)row * N + col)       = h0;
                *(__half2*)(C + (size_t)(row + 8) * N + col) = h1;
                if (FUSE_VT && col >= 2 * N_EMBD) {
                    const int dc = col - 2 * N_EMBD;        // 0..1023
                    const int bh = (row >> 11) * N_HEAD + (dc >> 6);
                    const int d  = dc & 63;
                    const int t  = row & (SEQ - 1);
                    __half* vb = vt + ((size_t)bh * HEADD + d) * SEQ;
                    vb[t]           = __low2half(h0);
                    vb[SEQ + t]     = __high2half(h0);
                    vb[t + 8]       = __low2half(h1);
                    vb[SEQ + t + 8] = __high2half(h1);
                }
            } else {
                float* C = (float*)Cv;
                float2 a = {v00, v01}, b2 = {v10, v11};
                *(float2*)(C + (size_t)row * N + col)       = a;
                *(float2*)(C + (size_t)(row + 8) * N + col) = b2;
            }
        }
    }
#undef PREFETCH
#undef LOAD_FRAGS
}

// ---------------------------------------------------------------------------
// Flash attention, causal, FP16 mma.sync, all-ldmatrix, f16x2 exp2 softmax.
// 4-stage KV ring, one barrier per PAIR of 64-key blocks; row-sum via
// ones-MMA. grid: (T/128 reversed, B*H). 256 threads = 8 warps.
// (unchanged from round 15)
// ---------------------------------------------------------------------------
#define KVS       72                                    // halves per row
#define KTILE_B   (64 * KVS * 2)                        // 9216 B
#define KVBUF_B   (2 * KTILE_B)                         // K + Vt per stage
#define PS        72
#define PSTRIP_B  (16 * PS * 2)                         // 2304 B per warp
#define ATTN_SMEM (4 * KVBUF_B + 8 * PSTRIP_B)          // 92160 B

__global__ __launch_bounds__(256, 2) void attn_mma(
    const __half* __restrict__ qkvh, const __half* __restrict__ vth,
    __half* __restrict__ att)
{
    extern __shared__ char smem[];
    __half* smh = (__half*)smem;
    const uint32_t sb = smem_u32(smem);

    const int qb = gridDim.x - 1 - blockIdx.x;   // heavy CTAs first
    const int b  = blockIdx.y >> 4;
    const int h  = blockIdx.y & 15;

    const int tid  = threadIdx.x;
    const int lane = tid & 31;
    const int warp = tid >> 5;
    const int gid  = lane >> 2;
    const int gtd  = lane & 3;
    const int wq   = warp * 16;

    const __half* kbase = qkvh + (size_t)(b * SEQ) * C3 + N_EMBD + h * HEADD;
    const __half* vtb   = vth + (size_t)((b * N_HEAD + h) * HEADD) * SEQ;

#define PREFETCH_KV(jb, buf)                                                   \
    {                                                                          \
        const __half* kp = kbase + (size_t)((jb) * 64) * C3;                   \
        const __half* vp = vtb + (jb) * 64;                                    \
        const uint32_t sK = sb + (buf) * KVBUF_B;                              \
        const uint32_t sV = sK + KTILE_B;                                      \
        _Pragma("unroll")                                                      \
        for (int i = 0; i < 2; i++) {                                          \
            int s = tid + i * 256;                                             \
            int r = s >> 3, p = s & 7;                                         \
            cp_async16(sK + r * (KVS * 2) + p * 16,                            \
                       kp + (size_t)r * C3 + p * 8);                           \
            cp_async16(sV + r * (KVS * 2) + p * 16,                            \
                       vp + (size_t)r * SEQ + p * 8);                          \
        }                                                                      \
        CP_COMMIT();                                                           \
    }

    PREFETCH_KV(0, 0);
    PREFETCH_KV(1, 1);

    // Q fragments (half2, scaled by exact 0.125)
    uint32_t qf[4][4];
    {
        const __half* qp = qkvh + (size_t)(b * SEQ + qb * 128) * C3 + h * HEADD;
        const int r0 = wq + gid, r1 = r0 + 8;
        const __half2 sc = __floats2half2_rn(0.125f, 0.125f);
#pragma unroll
        for (int ks = 0; ks < 4; ks++) {
            const int c = ks * 16 + gtd * 2;
            __half2 v;
            v = *(const __half2*)(qp + (size_t)r0 * C3 + c);
            qf[ks][0] = h2_bits(__hmul2(v, sc));
            v = *(const __half2*)(qp + (size_t)r1 * C3 + c);
            qf[ks][1] = h2_bits(__hmul2(v, sc));
            v = *(const __half2*)(qp + (size_t)r0 * C3 + c + 8);
            qf[ks][2] = h2_bits(__hmul2(v, sc));
            v = *(const __half2*)(qp + (size_t)r1 * C3 + c + 8);
            qf[ks][3] = h2_bits(__hmul2(v, sc));
        }
    }

    // per-warp P strip (after the 4 KV stages)
    __half* Pw = smh + (4 * KVBUF_B + warp * PSTRIP_B) / 2;
    const uint32_t sP = sb + 4 * KVBUF_B + warp * PSTRIP_B;
    const uint32_t bfrag_off = (uint32_t)((lane & 7) + ((lane >> 4) << 3)) * (KVS * 2) +
                               (((uint32_t)(lane >> 3) & 1) << 4);
    const uint32_t afrag_off = (uint32_t)(lane & 15) * (PS * 2) +
                               ((uint32_t)(lane >> 4) << 4);

    const uint32_t onesb[2] = {0x3C003C00u, 0x3C003C00u};   // fp16 1.0 x2

    float m0 = -1e30f, m1 = -1e30f, l0 = 0.f, l1 = 0.f;
    float o[8][4];
#pragma unroll
    for (int dt = 0; dt < 8; dt++)
#pragma unroll
        for (int r = 0; r < 4; r++) o[dt][r] = 0.f;

    const int dw  = 2 * qb + (warp >> 2);
    const int NJB = 2 * qb + 2;          // always even
    const int rowg0 = qb * 128 + wq + gid;
    const int rowg1 = rowg0 + 8;
    const float LOG2E = 1.4426950408889634f;

    for (int jb = 0; jb < NJB; jb += 2) {
        CP_WAIT(0);
        __syncthreads();
        if (jb + 2 < NJB) PREFETCH_KV(jb + 2, (jb + 2) & 3);
        if (jb + 3 < NJB) PREFETCH_KV(jb + 3, (jb + 3) & 3);

#pragma unroll
        for (int u = 0; u < 2; u++) {
            const int jj = jb + u;
            if (jj > dw) continue;

            const uint32_t sK = sb + (uint32_t)(jj & 3) * KVBUF_B;
            const uint32_t sV = sK + KTILE_B;

            float s[8][4];
#pragma unroll
            for (int nt = 0; nt < 8; nt++)
#pragma unroll
                for (int r = 0; r < 4; r++) s[nt][r] = 0.f;

#pragma unroll
            for (int ks = 0; ks < 4; ks++) {
                const uint32_t kb = (uint32_t)ks * 32;
#pragma unroll
                for (int ntp = 0; ntp < 4; ntp++) {
                    uint32_t kf[4];
                    ldsm_x4(kf, sK + (uint32_t)(ntp * 16) * (KVS * 2) +
                                 bfrag_off + kb);
                    mma_f16(s[2 * ntp],     qf[ks], kf);
                    mma_f16(s[2 * ntp + 1], qf[ks], kf + 2);
                }
            }

            if (jj == dw) {
#pragma unroll
                for (int nt = 0; nt < 8; nt++) {
                    const int cg = jj * 64 + nt * 8 + gtd * 2;
                    if (cg     > rowg0) s[nt][0] = -1e30f;
                    if (cg + 1 > rowg0) s[nt][1] = -1e30f;
                    if (cg     > rowg1) s[nt][2] = -1e30f;
                    if (cg + 1 > rowg1) s[nt][3] = -1e30f;
                }
            }

            float mx0 = -1e30f, mx1 = -1e30f;
#pragma unroll
            for (int nt = 0; nt < 8; nt++) {
                mx0 = fmaxf(mx0, fmaxf(s[nt][0], s[nt][1]));
                mx1 = fmaxf(mx1, fmaxf(s[nt][2], s[nt][3]));
            }
            mx0 = fmaxf(mx0, __shfl_xor_sync(0xffffffffu, mx0, 1));
            mx0 = fmaxf(mx0, __shfl_xor_sync(0xffffffffu, mx0, 2));
            mx1 = fmaxf(mx1, __shfl_xor_sync(0xffffffffu, mx1, 1));
            mx1 = fmaxf(mx1, __shfl_xor_sync(0xffffffffu, mx1, 2));

            const float mn0 = fmaxf(m0, mx0), mn1 = fmaxf(m1, mx1);
            const float a0 = __expf(m0 - mn0), a1 = __expf(m1 - mn1);
            m0 = mn0; m1 = mn1;

            const float nm0 = -mn0 * LOG2E, nm1 = -mn1 * LOG2E;
#pragma unroll
            for (int nt = 0; nt < 8; nt++) {
                float t0 = fmaf(s[nt][0], LOG2E, nm0);
                float t1 = fmaf(s[nt][1], LOG2E, nm0);
                float t2 = fmaf(s[nt][2], LOG2E, nm1);
                float t3 = fmaf(s[nt][3], LOG2E, nm1);
                *(__half2*)&Pw[gid * PS + nt * 8 + gtd * 2] =
                    h2exp2(__floats2half2_rn(t0, t1));
                *(__half2*)&Pw[(gid + 8) * PS + nt * 8 + gtd * 2] =
                    h2exp2(__floats2half2_rn(t2, t3));
            }

#pragma unroll
            for (int dt = 0; dt < 8; dt++) {
                o[dt][0] *= a0; o[dt][1] *= a0;
                o[dt][2] *= a1; o[dt][3] *= a1;
            }

            __syncwarp();

            float rsacc[4] = {0.f, 0.f, 0.f, 0.f};
#pragma unroll
            for (int cb = 0; cb < 4; cb++) {
                const uint32_t kb = (uint32_t)cb * 32;
                uint32_t pf[4];
                ldsm_x4(pf, sP + afrag_off + kb);
                mma_f16(rsacc, pf, onesb);       // row sum (all cols equal)
#pragma unroll
                for (int dtp = 0; dtp < 4; dtp++) {
                    uint32_t vf[4];
                    ldsm_x4(vf, sV + (uint32_t)(dtp * 16) * (KVS * 2) +
                                 bfrag_off + kb);
                    mma_f16(o[2 * dtp],     pf, vf);
                    mma_f16(o[2 * dtp + 1], pf, vf + 2);
                }
            }
            l0 = l0 * a0 + rsacc[0];
            l1 = l1 * a1 + rsacc[2];
        }
    }

    const float inv0 = 1.f / l0, inv1 = 1.f / l1;
    const size_t grow0 = (size_t)(b * SEQ + qb * 128 + wq + gid);
    const int colb = h * HEADD + gtd * 2;
#pragma unroll
    for (int dt = 0; dt < 8; dt++) {
        *(__half2*)(att + grow0 * N_EMBD + colb + dt * 8) =
            __floats2half2_rn(o[dt][0] * inv0, o[dt][1] * inv0);
        *(__half2*)(att + (grow0 + 8) * N_EMBD + colb + dt * 8) =
            __floats2half2_rn(o[dt][2] * inv1, o[dt][3] * inv1);
    }
#undef PREFETCH_KV
}

// ---------------------------------------------------------------------------
extern "C" void kernel_launch(void* const* d_in, const int* in_sizes, int n_in,
                              void* d_out, int out_size)
{
    const float* x     = (const float*)d_in[0];
    const float* W_qkv = (const float*)d_in[1];
    const float* b_qkv = (const float*)d_in[2];
    const float* W_out = (const float*)d_in[3];
    const float* b_out = (const float*)d_in[4];
    float* out = (float*)d_out;

    __half *qkvh, *atth, *xh, *wqth, *woth, *vth;
    cudaGetSymbolAddress((void**)&qkvh, g_qkvh);
    cudaGetSymbolAddress((void**)&atth, g_atth);
    cudaGetSymbolAddress((void**)&xh,   g_xh);
    cudaGetSymbolAddress((void**)&wqth, g_wqth);
    cudaGetSymbolAddress((void**)&woth, g_woth);
    cudaGetSymbolAddress((void**)&vth,  g_vth);

    cudaFuncSetAttribute((const void*)gemm_f16<true, true>,
                         cudaFuncAttributeMaxDynamicSharedMemorySize, GEMM_SMEM);
    cudaFuncSetAttribute((const void*)gemm_f16<false, false>,
                         cudaFuncAttributeMaxDynamicSharedMemorySize, GEMM_SMEM);
    cudaFuncSetAttribute((const void*)attn_mma,
                         cudaFuncAttributeMaxDynamicSharedMemorySize, ATTN_SMEM);

    // fused pre-pass: x->half + both weight transposes, one launch
    prepass<<<8192 + 3072 + 1024, 256>>>(x, (__half2*)xh, W_qkv, wqth,
                                         W_out, woth);

    // 1) qkv = x @ W_qkv + b_qkv  (half output + fused V^T scatter)
    gemm_f16<true, true><<<dim3(C3 / 64, ROWS / 128), 128, GEMM_SMEM>>>(
        xh, wqth, b_qkv, qkvh, vth, ROWS, C3, N_EMBD);
    // 2) attention (half output)
    attn_mma<<<dim3(SEQ / 128, BATCH * N_HEAD), 256, ATTN_SMEM>>>(qkvh, vth, atth);
    // 3) out = att @ W_out + b_out  (fp32 output)
    gemm_f16<false, false><<<dim3(N_EMBD / 64, ROWS / 128), 128, GEMM_SMEM>>>(
        atth, woth, b_out, out, nullptr, ROWS, N_EMBD, N_EMBD);
}

// round 17
// speedup vs baseline: 1.0642x; 1.0642x over previous
#include <cuda_runtime.h>
#include <cuda_fp16.h>
#include <cstdint>
#include <string.h>
#include <math.h>

#define N_EMBD 1024
#define N_HEAD 16
#define HEADD  64
#define BATCH  4
#define SEQ    2048
#define ROWS   (BATCH * SEQ)          // 8192
#define C3     (3 * N_EMBD)           // 3072

// scratch (allocation-free rule: device globals) — fp16 operand copies
__device__ __half g_qkvh[(size_t)ROWS * C3];        // qkv, half (V cols unused)
__device__ __half g_atth[(size_t)ROWS * N_EMBD];    // attention out, half
__device__ __half g_xh  [(size_t)ROWS * N_EMBD];    // x, half
__device__ __half g_wqth[(size_t)C3 * N_EMBD];      // W_qkv^T [3072,1024], half
__device__ __half g_woth[(size_t)N_EMBD * N_EMBD];  // W_out^T [1024,1024], half
__device__ __half g_vth [(size_t)BATCH * N_HEAD * HEADD * SEQ];  // V^T per head

// ---------------------------------------------------------------------------
__device__ __forceinline__ uint32_t h2_bits(__half2 v) {
    uint32_t u;
    memcpy(&u, &v, 4);
    return u;
}
__device__ __forceinline__ uint32_t smem_u32(const void* p) {
    uint32_t a;
    asm("{ .reg .u64 t; cvta.to.shared.u64 t, %1; cvt.u32.u64 %0, t; }" : "=r"(a) : "l"(p));
    return a;
}
__device__ __forceinline__ void cp_async16(uint32_t dst, const void* src) {
    asm volatile("cp.async.cg.shared.global [%0], [%1], 16;" :: "r"(dst), "l"(src));
}
#define CP_COMMIT() asm volatile("cp.async.commit_group;" ::: "memory")
#define CP_WAIT(n)  asm volatile("cp.async.wait_group %0;" :: "n"(n) : "memory")

__device__ __forceinline__ void mma_f16(float* d, const uint32_t* a, const uint32_t* b) {
    asm volatile(
        "mma.sync.aligned.m16n8k16.row.col.f32.f16.f16.f32 "
        "{%0,%1,%2,%3}, {%4,%5,%6,%7}, {%8,%9}, {%0,%1,%2,%3};"
        : "+f"(d[0]), "+f"(d[1]), "+f"(d[2]), "+f"(d[3])
        : "r"(a[0]), "r"(a[1]), "r"(a[2]), "r"(a[3]), "r"(b[0]), "r"(b[1]));
}
__device__ __forceinline__ void ldsm_x4(uint32_t* r, uint32_t addr) {
    asm volatile("ldmatrix.sync.aligned.m8n8.x4.shared.b16 {%0,%1,%2,%3}, [%4];"
                 : "=r"(r[0]), "=r"(r[1]), "=r"(r[2]), "=r"(r[3]) : "r"(addr));
}

// ---------------------------------------------------------------------------
// fused pre-pass: one launch does x->half convert + both weight transposes.
// ---------------------------------------------------------------------------
__device__ __forceinline__ void transpose_tile(const float* __restrict__ W,
                                               __half* __restrict__ Wt,
                                               int N, int nx, int ky,
                                               float (*t)[33]) {
    const int tx = threadIdx.x & 31, ty = threadIdx.x >> 5;
#pragma unroll
    for (int i = 0; i < 32; i += 8)
        t[ty + i][tx] = W[(size_t)(ky + ty + i) * N + nx + tx];
    __syncthreads();
#pragma unroll
    for (int i = 0; i < 32; i += 8)
        Wt[(size_t)(nx + ty + i) * 1024 + ky + tx] = __float2half_rn(t[tx][ty + i]);
}

__global__ __launch_bounds__(256) void prepass(
    const float* __restrict__ x, __half2* __restrict__ xh,
    const float* __restrict__ Wq, __half* __restrict__ wqt,
    const float* __restrict__ Wo, __half* __restrict__ wot)
{
    __shared__ float t[32][33];
    int bid = blockIdx.x;
    if (bid < 8192) {
        int i = bid * 256 + threadIdx.x;
        float4 v = ((const float4*)x)[i];
        xh[2 * i]     = __floats2half2_rn(v.x, v.y);
        xh[2 * i + 1] = __floats2half2_rn(v.z, v.w);
    } else if (bid < 8192 + 3072) {
        bid -= 8192;
        transpose_tile(Wq, wqt, C3, (bid % 96) * 32, (bid / 96) * 32, t);
    } else {
        bid -= 8192 + 3072;
        transpose_tile(Wo, wot, N_EMBD, (bid & 31) * 32, (bid >> 5) * 32, t);
    }
}

// ---------------------------------------------------------------------------
// FP16 mma.sync GEMM + bias: C[M,N] = A[M,K] @ Bt[N,K]^T + bias[N]
// 128x128 tile, 64x32 warp tile, BK=64 halves, 256 threads, 2 CTAs/SM,
// 3-stage cp.async pipeline, software-pipelined ldmatrix fragments.
// FUSE_VT: cols >= 2048 (V slice) go ONLY to vt[bh][d][t] (qkvh V cols are
// dead — attention reads V from vt exclusively).
// ---------------------------------------------------------------------------
#define TSH      72                              // halves per row (144 B)
#define T_STAGE  (128 * TSH * 2)                 // 18432 B per tile
#define GEMM_SMEM (3 * 2 * T_STAGE)              // 110592 B

template <bool HALF_OUT, bool FUSE_VT>
__global__ __launch_bounds__(256, 2) void gemm_f16(
    const __half* __restrict__ A, const __half* __restrict__ Bt,
    const float* __restrict__ bias, void* __restrict__ Cv,
    __half* __restrict__ vt,
    int M, int N, int K)
{
    extern __shared__ char smem[];
    const uint32_t sb = smem_u32(smem);

    const int tid  = threadIdx.x;
    const int lane = tid & 31;
    const int warp = tid >> 5;
    const int wm   = (warp >> 2) * 64;
    const int wn   = (warp & 3) * 32;

    const int m0 = blockIdx.y * 128;
    const int n0 = blockIdx.x * 128;

    const int gid = lane >> 2;
    const int gtd = lane & 3;

    float acc[4][4][4];
#pragma unroll
    for (int mi = 0; mi < 4; mi++)
#pragma unroll
        for (int ni = 0; ni < 4; ni++)
#pragma unroll
            for (int r = 0; r < 4; r++) acc[mi][ni][r] = 0.f;

    const uint32_t a_off = (uint32_t)(lane & 15) * (TSH * 2) +
                           ((uint32_t)(lane >> 4) << 4);
    const uint32_t b4_off = (uint32_t)((lane & 7) + ((lane >> 4) << 3)) * (TSH * 2) +
                            (((uint32_t)(lane >> 3) & 1) << 4);

#define PREFETCH(c, buf)                                                       \
    {                                                                          \
        const __half* Ag = A + (size_t)m0 * K + (c) * 64;                      \
        const __half* Bg = Bt + (size_t)n0 * K + (c) * 64;                     \
        const uint32_t pA = sb + (buf) * (2 * T_STAGE);                        \
        const uint32_t pB = pA + T_STAGE;                                      \
        _Pragma("unroll")                                                      \
        for (int i = 0; i < 4; i++) {                                          \
            int s  = tid + i * 256;                                            \
            int r  = s >> 3, p = s & 7;                                        \
            cp_async16(pA + r * (TSH * 2) + p * 16,                            \
                       Ag + (size_t)r * K + p * 8);                            \
            cp_async16(pB + r * (TSH * 2) + p * 16,                            \
                       Bg + (size_t)r * K + p * 8);                            \
        }                                                                      \
        CP_COMMIT();                                                           \
    }

#define LOAD_FRAGS(kk, bufi)                                                   \
    {                                                                          \
        const uint32_t kb = (uint32_t)(kk) * 32;                               \
        _Pragma("unroll")                                                      \
        for (int mi = 0; mi < 4; mi++)                                         \
            ldsm_x4(af[bufi][mi],                                              \
                    sA + (uint32_t)(wm + mi * 16) * (TSH * 2) + a_off + kb);   \
        _Pragma("unroll")                                                      \
        for (int p = 0; p < 2; p++)                                            \
            ldsm_x4(bf[bufi][p],                                               \
                    sB + (uint32_t)(wn + p * 16) * (TSH * 2) + b4_off + kb);   \
    }

    uint32_t af[2][4][4];
    uint32_t bf[2][2][4];

    const int NK = K >> 6;   // BK = 64 halves
    PREFETCH(0, 0);
    PREFETCH(1, 1);

    for (int c = 0; c < NK; c++) {
        if (c + 1 < NK) CP_WAIT(1); else CP_WAIT(0);
        __syncthreads();
        if (c + 2 < NK) PREFETCH(c + 2, (c + 2) % 3);

        const int buf = c % 3;
        const uint32_t sA = sb + buf * (2 * T_STAGE);
        const uint32_t sB = sA + T_STAGE;

        LOAD_FRAGS(0, 0);
#pragma unroll
        for (int kk = 0; kk < 4; kk++) {        // 4 x k16
            if (kk < 3) LOAD_FRAGS(kk + 1, (kk + 1) & 1);
            const int cur = kk & 1;
#pragma unroll
            for (int mi = 0; mi < 4; mi++)
#pragma unroll
                for (int ni = 0; ni < 4; ni++)
                    mma_f16(acc[mi][ni], af[cur][mi],
                            &bf[cur][ni >> 1][(ni & 1) << 1]);
        }
    }

    // epilogue: fp32 bias add; store half or float; V slice -> vt only
#pragma unroll
    for (int mi = 0; mi < 4; mi++) {
#pragma unroll
        for (int ni = 0; ni < 4; ni++) {
            const int row = m0 + wm + mi * 16 + gid;
            const int col = n0 + wn + ni * 8 + (gtd << 1);
            const float b0 = bias[col];
            const float b1 = bias[col + 1];
            float v00 = acc[mi][ni][0] + b0, v01 = acc[mi][ni][1] + b1;
            float v10 = acc[mi][ni][2] + b0, v11 = acc[mi][ni][3] + b1;
            if (HALF_OUT) {
                __half2 h0 = __floats2half2_rn(v00, v01);
                __half2 h1 = __floats2half2_rn(v10, v11);
                if (FUSE_VT && col >= 2 * N_EMBD) {
                    // V slice: write ONLY transposed vt (qkvh V cols dead)
                    const int dc = col - 2 * N_EMBD;        // 0..1023
                    const int bh = (row >> 11) * N_HEAD + (dc >> 6);
                    const int d  = dc & 63;
                    const int t  = row & (SEQ - 1);
                    __half* vb = vt + ((size_t)bh * HEADD + d) * SEQ;
                    vb[t]           = __low2half(h0);
                    vb[SEQ + t]     = __high2half(h0);
                    vb[t + 8]       = __low2half(h1);
                    vb[SEQ + t + 8] = __high2half(h1);
                } else {
                    __half* C = (__half*)Cv;
                    *(__half2*)(C + (size_t)row * N + col)       = h0;
                    *(__half2*)(C + (size_t)(row + 8) * N + col) = h1;
                }
            } else {
                float* C = (float*)Cv;
                float2 a = {v00, v01}, b2 = {v10, v11};
                *(float2*)(C + (size_t)row * N + col)       = a;
                *(float2*)(C + (size_t)(row + 8) * N + col) = b2;
            }
        }
    }
#undef PREFETCH
#undef LOAD_FRAGS
}

// ---------------------------------------------------------------------------
// Flash attention, causal, FP16 mma.sync, all-ldmatrix, f16x2 exp2 softmax.
// 4-stage KV ring, one barrier per PAIR of 64-key blocks; row-sum via
// ones-MMA. grid: (T/128 reversed, B*H). 256 threads = 8 warps.
// (unchanged from round 15)
// ---------------------------------------------------------------------------
#define KVS       72                                    // halves per row
#define KTILE_B   (64 * KVS * 2)                        // 9216 B
#define KVBUF_B   (2 * KTILE_B)                         // K + Vt per stage
#define PS        72
#define PSTRIP_B  (16 * PS * 2)                         // 2304 B per warp
#define ATTN_SMEM (4 * KVBUF_B + 8 * PSTRIP_B)          // 92160 B

__global__ __launch_bounds__(256, 2) void attn_mma(
    const __half* __restrict__ qkvh, const __half* __restrict__ vth,
    __half* __restrict__ att)
{
    extern __shared__ char smem[];
    __half* smh = (__half*)smem;
    const uint32_t sb = smem_u32(smem);

    const int qb = gridDim.x - 1 - blockIdx.x;   // heavy CTAs first
    const int b  = blockIdx.y >> 4;
    const int h  = blockIdx.y & 15;

    const int tid  = threadIdx.x;
    const int lane = tid & 31;
    const int warp = tid >> 5;
    const int gid  = lane >> 2;
    const int gtd  = lane & 3;
    const int wq   = warp * 16;

    const __half* kbase = qkvh + (size_t)(b * SEQ) * C3 + N_EMBD + h * HEADD;
    const __half* vtb   = vth + (size_t)((b * N_HEAD + h) * HEADD) * SEQ;

#define PREFETCH_KV(jb, buf)                                                   \
    {                                                                          \
        const __half* kp = kbase + (size_t)((jb) * 64) * C3;                   \
        const __half* vp = vtb + (jb) * 64;                                    \
        const uint32_t sK = sb + (buf) * KVBUF_B;                              \
        const uint32_t sV = sK + KTILE_B;                                      \
        _Pragma("unroll")                                                      \
        for (int i = 0; i < 2; i++) {                                          \
            int s = tid + i * 256;                                             \
            int r = s >> 3, p = s & 7;                                         \
            cp_async16(sK + r * (KVS * 2) + p * 16,                            \
                       kp + (size_t)r * C3 + p * 8);                           \
            cp_async16(sV + r * (KVS * 2) + p * 16,                            \
                       vp + (size_t)r * SEQ + p * 8);                          \
        }                                                                      \
        CP_COMMIT();                                                           \
    }

    PREFETCH_KV(0, 0);
    PREFETCH_KV(1, 1);

    // Q fragments (half2, scaled by exact 0.125)
    uint32_t qf[4][4];
    {
        const __half* qp = qkvh + (size_t)(b * SEQ + qb * 128) * C3 + h * HEADD;
        const int r0 = wq + gid, r1 = r0 + 8;
        const __half2 sc = __floats2half2_rn(0.125f, 0.125f);
#pragma unroll
        for (int ks = 0; ks < 4; ks++) {
            const int c = ks * 16 + gtd * 2;
            __half2 v;
            v = *(const __half2*)(qp + (size_t)r0 * C3 + c);
            qf[ks][0] = h2_bits(__hmul2(v, sc));
            v = *(const __half2*)(qp + (size_t)r1 * C3 + c);
            qf[ks][1] = h2_bits(__hmul2(v, sc));
            v = *(const __half2*)(qp + (size_t)r0 * C3 + c + 8);
            qf[ks][2] = h2_bits(__hmul2(v, sc));
            v = *(const __half2*)(qp + (size_t)r1 * C3 + c + 8);
            qf[ks][3] = h2_bits(__hmul2(v, sc));
        }
    }

    // per-warp P strip (after the 4 KV stages)
    __half* Pw = smh + (4 * KVBUF_B + warp * PSTRIP_B) / 2;
    const uint32_t sP = sb + 4 * KVBUF_B + warp * PSTRIP_B;
    const uint32_t bfrag_off = (uint32_t)((lane & 7) + ((lane >> 4) << 3)) * (KVS * 2) +
                               (((uint32_t)(lane >> 3) & 1) << 4);
    const uint32_t afrag_off = (uint32_t)(lane & 15) * (PS * 2) +
                               ((uint32_t)(lane >> 4) << 4);

    const uint32_t onesb[2] = {0x3C003C00u, 0x3C003C00u};   // fp16 1.0 x2

    float m0 = -1e30f, m1 = -1e30f, l0 = 0.f, l1 = 0.f;
    float o[8][4];
#pragma unroll
    for (int dt = 0; dt < 8; dt++)
#pragma unroll
        for (int r = 0; r < 4; r++) o[dt][r] = 0.f;

    const int dw  = 2 * qb + (warp >> 2);
    const int NJB = 2 * qb + 2;          // always even
    const int rowg0 = qb * 128 + wq + gid;
    const int rowg1 = rowg0 + 8;
    const float LOG2E = 1.4426950408889634f;

    for (int jb = 0; jb < NJB; jb += 2) {
        CP_WAIT(0);
        __syncthreads();
        if (jb + 2 < NJB) PREFETCH_KV(jb + 2, (jb + 2) & 3);
        if (jb + 3 < NJB) PREFETCH_KV(jb + 3, (jb + 3) & 3);

#pragma unroll
        for (int u = 0; u < 2; u++) {
            const int jj = jb + u;
            if (jj > dw) continue;

            const uint32_t sK = sb + (uint32_t)(jj & 3) * KVBUF_B;
            const uint32_t sV = sK + KTILE_B;

            float s[8][4];
#pragma unroll
            for (int nt = 0; nt < 8; nt++)
#pragma unroll
                for (int r = 0; r < 4; r++) s[nt][r] = 0.f;

#pragma unroll
            for (int ks = 0; ks < 4; ks++) {
                const uint32_t kb = (uint32_t)ks * 32;
#pragma unroll
                for (int ntp = 0; ntp < 4; ntp++) {
                    uint32_t kf[4];
                    ldsm_x4(kf, sK + (uint32_t)(ntp * 16) * (KVS * 2) +
                                 bfrag_off + kb);
                    mma_f16(s[2 * ntp],     qf[ks], kf);
                    mma_f16(s[2 * ntp + 1], qf[ks], kf + 2);
                }
            }

            if (jj == dw) {
#pragma unroll
                for (int nt = 0; nt < 8; nt++) {
                    const int cg = jj * 64 + nt * 8 + gtd * 2;
                    if (cg     > rowg0) s[nt][0] = -1e30f;
                    if (cg + 1 > rowg0) s[nt][1] = -1e30f;
                    if (cg     > rowg1) s[nt][2] = -1e30f;
                    if (cg + 1 > rowg1) s[nt][3] = -1e30f;
                }
            }

            float mx0 = -1e30f, mx1 = -1e30f;
#pragma unroll
            for (int nt = 0; nt < 8; nt++) {
                mx0 = fmaxf(mx0, fmaxf(s[nt][0], s[nt][1]));
                mx1 = fmaxf(mx1, fmaxf(s[nt][2], s[nt][3]));
            }
            mx0 = fmaxf(mx0, __shfl_xor_sync(0xffffffffu, mx0, 1));
            mx0 = fmaxf(mx0, __shfl_xor_sync(0xffffffffu, mx0, 2));
            mx1 = fmaxf(mx1, __shfl_xor_sync(0xffffffffu, mx1, 1));
            mx1 = fmaxf(mx1, __shfl_xor_sync(0xffffffffu, mx1, 2));

            const float mn0 = fmaxf(m0, mx0), mn1 = fmaxf(m1, mx1);
            const float a0 = __expf(m0 - mn0), a1 = __expf(m1 - mn1);
            m0 = mn0; m1 = mn1;

            const float nm0 = -mn0 * LOG2E, nm1 = -mn1 * LOG2E;
#pragma unroll
            for (int nt = 0; nt < 8; nt++) {
                float t0 = fmaf(s[nt][0], LOG2E, nm0);
                float t1 = fmaf(s[nt][1], LOG2E, nm0);
                float t2 = fmaf(s[nt][2], LOG2E, nm1);
                float t3 = fmaf(s[nt][3], LOG2E, nm1);
                *(__half2*)&Pw[gid * PS + nt * 8 + gtd * 2] =
                    h2exp2(__floats2half2_rn(t0, t1));
                *(__half2*)&Pw[(gid + 8) * PS + nt * 8 + gtd * 2] =
                    h2exp2(__floats2half2_rn(t2, t3));
            }

#pragma unroll
            for (int dt = 0; dt < 8; dt++) {
                o[dt][0] *= a0; o[dt][1] *= a0;
                o[dt][2] *= a1; o[dt][3] *= a1;
            }

            __syncwarp();

            float rsacc[4] = {0.f, 0.f, 0.f, 0.f};
#pragma unroll
            for (int cb = 0; cb < 4; cb++) {
                const uint32_t kb = (uint32_t)cb * 32;
                uint32_t pf[4];
                ldsm_x4(pf, sP + afrag_off + kb);
                mma_f16(rsacc, pf, onesb);       // row sum (all cols equal)
#pragma unroll
                for (int dtp = 0; dtp < 4; dtp++) {
                    uint32_t vf[4];
                    ldsm_x4(vf, sV + (uint32_t)(dtp * 16) * (KVS * 2) +
                                 bfrag_off + kb);
                    mma_f16(o[2 * dtp],     pf, vf);
                    mma_f16(o[2 * dtp + 1], pf, vf + 2);
                }
            }
            l0 = l0 * a0 + rsacc[0];
            l1 = l1 * a1 + rsacc[2];
        }
    }

    const float inv0 = 1.f / l0, inv1 = 1.f / l1;
    const size_t grow0 = (size_t)(b * SEQ + qb * 128 + wq + gid);
    const int colb = h * HEADD + gtd * 2;
#pragma unroll
    for (int dt = 0; dt < 8; dt++) {
        *(__half2*)(att + grow0 * N_EMBD + colb + dt * 8) =
            __floats2half2_rn(o[dt][0] * inv0, o[dt][1] * inv0);
        *(__half2*)(att + (grow0 + 8) * N_EMBD + colb + dt * 8) =
            __floats2half2_rn(o[dt][2] * inv1, o[dt][3] * inv1);
    }
#undef PREFETCH_KV
}

// ---------------------------------------------------------------------------
extern "C" void kernel_launch(void* const* d_in, const int* in_sizes, int n_in,
                              void* d_out, int out_size)
{
    const float* x     = (const float*)d_in[0];
    const float* W_qkv = (const float*)d_in[1];
    const float* b_qkv = (const float*)d_in[2];
    const float* W_out = (const float*)d_in[3];
    const float* b_out = (const float*)d_in[4];
    float* out = (float*)d_out;

    __half *qkvh, *atth, *xh, *wqth, *woth, *vth;
    cudaGetSymbolAddress((void**)&qkvh, g_qkvh);
    cudaGetSymbolAddress((void**)&atth, g_atth);
    cudaGetSymbolAddress((void**)&xh,   g_xh);
    cudaGetSymbolAddress((void**)&wqth, g_wqth);
    cudaGetSymbolAddress((void**)&woth, g_woth);
    cudaGetSymbolAddress((void**)&vth,  g_vth);

    cudaFuncSetAttribute((const void*)gemm_f16<true, true>,
                         cudaFuncAttributeMaxDynamicSharedMemorySize, GEMM_SMEM);
    cudaFuncSetAttribute((const void*)gemm_f16<false, false>,
                         cudaFuncAttributeMaxDynamicSharedMemorySize, GEMM_SMEM);
    cudaFuncSetAttribute((const void*)attn_mma,
                         cudaFuncAttributeMaxDynamicSharedMemorySize, ATTN_SMEM);

    // fused pre-pass: x->half + both weight transposes, one launch
    prepass<<<8192 + 3072 + 1024, 256>>>(x, (__half2*)xh, W_qkv, wqth,
                                         W_out, woth);

    // 1) qkv = x @ W_qkv + b_qkv  (half output; V slice -> vt only)
    gemm_f16<true, true><<<dim3(C3 / 128, ROWS / 128), 256, GEMM_SMEM>>>(
        xh, wqth, b_qkv, qkvh, vth, ROWS, C3, N_EMBD);
    // 2) attention (half output)
    attn_mma<<<dim3(SEQ / 128, BATCH * N_HEAD), 256, ATTN_SMEM>>>(qkvh, vth, atth);
    // 3) out = att @ W_out + b_out  (fp32 output)
    gemm_f16<false, false><<<dim3(N_EMBD / 128, ROWS / 128), 256, GEMM_SMEM>>>(
        atth, woth, b_out, out, nullptr, ROWS, N_EMBD, N_EMBD);
}